// round 16
// baseline (speedup 1.0000x reference)
#include <cuda_runtime.h>
#include <cuda_fp16.h>
#include <cstdint>

// ============================================================================
// Cl(3,0) steerable geometric product layer — baseline-PTX tensor cores.
// fp16 mma.sync.m16n8k16, persistent CTAs (1/SM), CTA tile 256x128,
// warp tile 64x64 (high ILP: 32-64 mma per ldsm batch).
//   gemm_xr : A split hi/lo (2 products), 2-stage 80KB pipeline
//   gemm_bil: bilinear+left single-product, 3-stage 48KB, 1 barrier/chunk
// ============================================================================

#define BDIM   2048
#define NIN    512
#define PLANE  (BDIM * NIN)
#define WSLICE (512 * 512)

#define QOFF0 0
#define QOFF1 4194304
#define QOFF2 23068672
#define QOFF3 41943040
#define QTOT  46137344

#define WBOFF0 0
#define WBOFF1 1048576
#define WBOFF2 2621440
#define WBOFF3 4194304
#define WBTOT  5242880

__constant__ int c_porder[20] = {0,4,10,16, 1,5,6,11,12,17, 2,7,8,13,14,18, 3,9,15,19};
__constant__ int c_grade[8]   = {0,1,1,1,2,2,2,3};
__constant__ int c_kb_base[20] = {
    WBOFF0+0, WBOFF0+512, WBOFF0+1024, WBOFF0+1536,
    WBOFF1+0, WBOFF1+512, WBOFF1+1024, WBOFF1+1536, WBOFF1+2048, WBOFF1+2560,
    WBOFF2+0, WBOFF2+512, WBOFF2+1024, WBOFF2+1536, WBOFF2+2048, WBOFF2+2560,
    WBOFF3+0, WBOFF3+512, WBOFF3+1024, WBOFF3+1536};
__constant__ int c_kb_K[20] = {2048,2048,2048,2048, 3072,3072,3072,3072,3072,3072,
                               3072,3072,3072,3072,3072,3072, 2048,2048,2048,2048};

__device__ __align__(256) __half g_XTh[8 * PLANE];
__device__ __align__(256) __half g_XTl[8 * PLANE];
__device__ __align__(256) __half g_WR [4 * WSLICE];
__device__ __align__(256) __half g_WL [4 * WSLICE];
__device__ __align__(256) __half g_WB [WBTOT];
__device__ __align__(256) __half g_Q  [QTOT];
__device__ float g_XR  [8 * PLANE];
__device__ float g_OUT8[8 * PLANE];
__device__ int   g_cnt_xr;
__device__ int   g_cnt_bil;

// ---------------------------------------------------------------------------
__device__ __forceinline__ uint32_t s2u(const void* p) {
    return (uint32_t)__cvta_generic_to_shared(p);
}
__device__ __forceinline__ void cp16(uint32_t dst, const void* src) {
    asm volatile("cp.async.cg.shared.global [%0], [%1], 16;\n" :: "r"(dst), "l"(src));
}
#define CP_COMMIT() asm volatile("cp.async.commit_group;\n" ::: "memory")
#define CP_WAIT1()  asm volatile("cp.async.wait_group 1;\n" ::: "memory")
#define CP_WAIT0()  asm volatile("cp.async.wait_group 0;\n" ::: "memory")

__device__ __forceinline__ void ldsm4(uint32_t* r, uint32_t addr) {
    asm volatile("ldmatrix.sync.aligned.m8n8.x4.shared.b16 {%0,%1,%2,%3}, [%4];"
                 : "=r"(r[0]), "=r"(r[1]), "=r"(r[2]), "=r"(r[3]) : "r"(addr));
}
__device__ __forceinline__ void mma_fp16(float* c, const uint32_t* a,
                                         uint32_t b0, uint32_t b1) {
    asm volatile(
        "mma.sync.aligned.m16n8k16.row.col.f32.f16.f16.f32 "
        "{%0,%1,%2,%3}, {%4,%5,%6,%7}, {%8,%9}, {%0,%1,%2,%3};"
        : "+f"(c[0]), "+f"(c[1]), "+f"(c[2]), "+f"(c[3])
        : "r"(a[0]), "r"(a[1]), "r"(a[2]), "r"(a[3]), "r"(b0), "r"(b1));
}

#define SWZ(o) ((o) ^ (((o) >> 3) & 0x70))

// XR: stage = Ah 32KB @0 + Al 32KB @32768 + B 16KB @65536 = 80KB, 2 stages
#define XR_STAGE 81920u
#define XR_SMEM  163840
// BIL: stage = A 32KB @0 + B 16KB @32768 = 48KB, 3 stages
#define BIL_STAGE 49152u
#define BIL_SMEM  147456

// ---------------------------------------------------------------------------
// XR GEMM (persistent): XR[z] = (XTh[z]+XTl[z]) @ WR[g(z)], 2 products.
// 256 tiles of 256x128 (z 8 x mb 8 x cb 4). 8 warps: 4M x 2N, warp 64x64.
// ---------------------------------------------------------------------------
__global__ void __launch_bounds__(256, 1)
gemm_xr() {
    extern __shared__ __align__(1024) char smem[];
    __shared__ int s_t;
    uint32_t sb = s2u(smem);
    int tid = threadIdx.x, lane = tid & 31, wid = tid >> 5;
    int wm = wid & 3, wn = wid >> 2;

    int a_rowb = wm * 64 + (lane & 15);
    int b_rowb = wn * 64 + (lane & 7) + ((lane >> 4) << 3);
    uint32_t a_colp = (uint32_t)((lane >> 4) << 4);
    uint32_t b_colp = (uint32_t)(((lane >> 3) & 1) << 4);
    uint32_t xmask  = (uint32_t)((lane & 7) << 4);

    for (;;) {
        if (tid == 0) s_t = atomicAdd(&g_cnt_xr, 1);
        __syncthreads();
        int t = s_t;
        __syncthreads();
        if (t >= 256) break;

        int z = t & 7, r2 = t >> 3;
        int cb = r2 & 3, mb = r2 >> 2;
        int row0 = mb * 256, col0 = cb * 128;
        int g = c_grade[z];
        const __half* Ah = g_XTh + (size_t)z * PLANE;
        const __half* Al = g_XTl + (size_t)z * PLANE;
        const __half* B  = g_WR  + (size_t)g * WSLICE;

        float acc[4][8][4];
#pragma unroll
        for (int mt = 0; mt < 4; mt++)
#pragma unroll
            for (int nt = 0; nt < 8; nt++)
#pragma unroll
                for (int q = 0; q < 4; q++) acc[mt][nt][q] = 0.0f;

        auto load = [&](int buf, int kt) {
            uint32_t st = sb + buf * XR_STAGE;
#pragma unroll
            for (int i = 0; i < 8; i++) {          // A: 256 rows x 128B, hi+lo
                int u = i * 256 + tid;
                int r = u >> 3, c16 = u & 7;
                uint32_t so = SWZ((uint32_t)((r << 7) + (c16 << 4)));
                size_t go = (size_t)(row0 + r) * 512 + kt + (c16 << 3);
                cp16(st + so,          Ah + go);
                cp16(st + 32768u + so, Al + go);
            }
#pragma unroll
            for (int i = 0; i < 4; i++) {          // B: 128 rows x 128B
                int u = i * 256 + tid;
                int r = u >> 3, c16 = u & 7;
                uint32_t so = SWZ((uint32_t)((r << 7) + (c16 << 4)));
                cp16(st + 65536u + so, B + (size_t)(col0 + r) * 512 + kt + (c16 << 3));
            }
        };

        load(0, 0);
        CP_COMMIT();
        const int nch = 8;
        for (int c = 0; c < nch; c++) {
            int buf = c & 1;
            if (c + 1 < nch) { load(buf ^ 1, (c + 1) << 6); CP_COMMIT(); CP_WAIT1(); }
            else             { CP_WAIT0(); }
            __syncthreads();

            uint32_t st  = sb + buf * XR_STAGE;
            uint32_t sAh = st, sAl = st + 32768u, sB = st + 65536u;
#pragma unroll
            for (int ks = 0; ks < 4; ks++) {
                uint32_t acol = ((uint32_t)(ks << 5) | a_colp) ^ xmask;
                uint32_t bcol = ((uint32_t)(ks << 5) | b_colp) ^ xmask;
                uint32_t afh[4][4], afl[4][4], bf[4][4];
#pragma unroll
                for (int mt = 0; mt < 4; mt++)
                    ldsm4(afh[mt], sAh + (uint32_t)((a_rowb + mt * 16) << 7) + acol);
#pragma unroll
                for (int mt = 0; mt < 4; mt++)
                    ldsm4(afl[mt], sAl + (uint32_t)((a_rowb + mt * 16) << 7) + acol);
#pragma unroll
                for (int bt = 0; bt < 4; bt++)
                    ldsm4(bf[bt], sB + (uint32_t)((b_rowb + bt * 16) << 7) + bcol);
#pragma unroll
                for (int mt = 0; mt < 4; mt++)
#pragma unroll
                    for (int nt = 0; nt < 8; nt++)
                        mma_fp16(acc[mt][nt], afh[mt], bf[nt >> 1][(nt & 1) * 2],
                                 bf[nt >> 1][(nt & 1) * 2 + 1]);
#pragma unroll
                for (int mt = 0; mt < 4; mt++)
#pragma unroll
                    for (int nt = 0; nt < 8; nt++)
                        mma_fp16(acc[mt][nt], afl[mt], bf[nt >> 1][(nt & 1) * 2],
                                 bf[nt >> 1][(nt & 1) * 2 + 1]);
            }
            __syncthreads();
        }

        int gr = row0 + wm * 64 + (lane >> 2);
        int gc = col0 + wn * 64 + (lane & 3) * 2;
        float* base = g_XR + (size_t)z * PLANE;
#pragma unroll
        for (int mt = 0; mt < 4; mt++) {
            int r0 = gr + mt * 16;
#pragma unroll
            for (int nt = 0; nt < 8; nt++) {
                int cc = gc + nt * 8;
                *(float2*)(base + (size_t)r0 * 512 + cc) =
                    make_float2(acc[mt][nt][0], acc[mt][nt][1]);
                *(float2*)(base + (size_t)(r0 + 8) * 512 + cc) =
                    make_float2(acc[mt][nt][2], acc[mt][nt][3]);
            }
        }
    }
}

// ---------------------------------------------------------------------------
// Fused bilinear + left GEMM (persistent, longest-first, 3-stage, 1 barrier).
// 256 tiles of 256x128: t<96 g1, <192 g2, <224 g0, else g3.
// ---------------------------------------------------------------------------
__global__ void __launch_bounds__(256, 1)
gemm_bil(const float* __restrict__ bias) {
    extern __shared__ __align__(1024) char smem[];
    __shared__ int s_t;
    uint32_t sb = s2u(smem);
    int tid = threadIdx.x, lane = tid & 31, wid = tid >> 5;
    int wm = wid & 3, wn = wid >> 2;

    int a_rowb = wm * 64 + (lane & 15);
    int b_rowb = wn * 64 + (lane & 7) + ((lane >> 4) << 3);
    uint32_t a_colp = (uint32_t)((lane >> 4) << 4);
    uint32_t b_colp = (uint32_t)(((lane >> 3) & 1) << 4);
    uint32_t xmask  = (uint32_t)((lane & 7) << 4);

    for (;;) {
        if (tid == 0) s_t = atomicAdd(&g_cnt_bil, 1);
        __syncthreads();
        int t = s_t;
        __syncthreads();
        if (t >= 256) break;

        int g, u;
        if      (t < 96)  { g = 1; u = t; }
        else if (t < 192) { g = 2; u = t - 96; }
        else if (t < 224) { g = 0; u = t - 192; }
        else              { g = 3; u = t - 224; }
        int rb = u >> 2, cb = u & 3;

        int Kq, s, pb;
        size_t qo; int wo;
        if      (g == 0) { Kq = 2048; s = 1; pb = 0; qo = QOFF0; wo = WBOFF0; }
        else if (g == 1) { Kq = 3072; s = 3; pb = 1; qo = QOFF1; wo = WBOFF1; }
        else if (g == 2) { Kq = 3072; s = 3; pb = 4; qo = QOFF2; wo = WBOFF2; }
        else             { Kq = 2048; s = 1; pb = 7; qo = QOFF3; wo = WBOFF3; }
        int row0 = rb * 256, col0 = cb * 128;
        const __half* Aq = g_Q + qo;
        const __half* Bq = g_WB + wo;
        const __half* Bl = g_WL + (size_t)g * WSLICE;

        int nch_q = Kq >> 6;
        int nch   = nch_q + 8;

        float acc[4][8][4];
#pragma unroll
        for (int mt = 0; mt < 4; mt++)
#pragma unroll
            for (int nt = 0; nt < 8; nt++)
#pragma unroll
                for (int q = 0; q < 4; q++) acc[mt][nt][q] = 0.0f;

        auto load = [&](int buf, int ci) {
            uint32_t st = sb + buf * BIL_STAGE;
            int kt = ci << 6;
            if (ci < nch_q) {
#pragma unroll
                for (int i = 0; i < 8; i++) {
                    int v = i * 256 + tid;
                    int r = v >> 3, c16 = v & 7;
                    uint32_t so = SWZ((uint32_t)((r << 7) + (c16 << 4)));
                    cp16(st + so, Aq + (size_t)(row0 + r) * Kq + kt + (c16 << 3));
                }
#pragma unroll
                for (int i = 0; i < 4; i++) {
                    int v = i * 256 + tid;
                    int r = v >> 3, c16 = v & 7;
                    uint32_t so = SWZ((uint32_t)((r << 7) + (c16 << 4)));
                    cp16(st + 32768u + so,
                         Bq + (size_t)(col0 + r) * Kq + kt + (c16 << 3));
                }
            } else {
                int kk = kt - Kq;
#pragma unroll
                for (int i = 0; i < 8; i++) {
                    int v = i * 256 + tid;
                    int r = v >> 3, c16 = v & 7;
                    uint32_t so = SWZ((uint32_t)((r << 7) + (c16 << 4)));
                    int rr = row0 + r, bb, jj;
                    if (s == 1) { bb = rr; jj = 0; }
                    else        { bb = rr / 3; jj = rr - bb * 3; }
                    cp16(st + so, g_XTh + (size_t)(pb + jj) * PLANE
                                        + (size_t)bb * 512 + kk + (c16 << 3));
                }
#pragma unroll
                for (int i = 0; i < 4; i++) {
                    int v = i * 256 + tid;
                    int r = v >> 3, c16 = v & 7;
                    uint32_t so = SWZ((uint32_t)((r << 7) + (c16 << 4)));
                    cp16(st + 32768u + so,
                         Bl + (size_t)(col0 + r) * 512 + kk + (c16 << 3));
                }
            }
        };

        load(0, 0); CP_COMMIT();
        load(1, 1); CP_COMMIT();
        for (int c = 0; c < nch; c++) {
            if (c + 1 < nch) CP_WAIT1(); else CP_WAIT0();
            __syncthreads();

            uint32_t st = sb + (uint32_t)(c % 3) * BIL_STAGE;
            uint32_t sA = st, sB = st + 32768u;
#pragma unroll
            for (int ks = 0; ks < 4; ks++) {
                uint32_t acol = ((uint32_t)(ks << 5) | a_colp) ^ xmask;
                uint32_t bcol = ((uint32_t)(ks << 5) | b_colp) ^ xmask;
                uint32_t af[4][4], bf[4][4];
#pragma unroll
                for (int mt = 0; mt < 4; mt++)
                    ldsm4(af[mt], sA + (uint32_t)((a_rowb + mt * 16) << 7) + acol);
#pragma unroll
                for (int bt = 0; bt < 4; bt++)
                    ldsm4(bf[bt], sB + (uint32_t)((b_rowb + bt * 16) << 7) + bcol);
#pragma unroll
                for (int mt = 0; mt < 4; mt++)
#pragma unroll
                    for (int nt = 0; nt < 8; nt++)
                        mma_fp16(acc[mt][nt], af[mt], bf[nt >> 1][(nt & 1) * 2],
                                 bf[nt >> 1][(nt & 1) * 2 + 1]);
            }
            // issue load for stage c+2 AFTER compute (3-stage: race-free with
            // chunk c-1 users — all passed this iteration's top barrier)
            if (c + 2 < nch) { load((c + 2) % 3, c + 2); CP_COMMIT(); }
        }

        int gr = row0 + wm * 64 + (lane >> 2);
        int gc = col0 + wn * 64 + (lane & 3) * 2;
        bool addb = (g == 0);
#pragma unroll
        for (int mt = 0; mt < 4; mt++) {
#pragma unroll
            for (int half = 0; half < 2; half++) {
                int r = gr + mt * 16 + half * 8;
                int bb, jj;
                if (s == 1) { bb = r; jj = 0; } else { bb = r / 3; jj = r - bb * 3; }
                float* base = g_OUT8 + (size_t)(pb + jj) * PLANE + (size_t)bb * 512;
#pragma unroll
                for (int nt = 0; nt < 8; nt++) {
                    int cc = gc + nt * 8;
                    float bx = 0.f, by = 0.f;
                    if (addb) { bx = bias[cc]; by = bias[cc + 1]; }
                    *(float2*)(base + cc) =
                        make_float2(acc[mt][nt][half * 2] + bx,
                                    acc[mt][nt][half * 2 + 1] + by);
                }
            }
        }
    }
}

// ---------------------------------------------------------------------------
// Elementwise kernels
// ---------------------------------------------------------------------------
__device__ __forceinline__ void hsplit(float v, __half* h, __half* l) {
    __half hh = __float2half_rn(v);
    *h = hh;
    *l = __float2half_rn(v - __half2float(hh));
}

// blocks [0,4096): x split | [4096,5120): weight transpose | [5120,6144): WR/WL
__global__ void prep_kernel(const float* __restrict__ x,
                            const float* __restrict__ weight,
                            const float* __restrict__ w_right,
                            const float* __restrict__ w_left) {
    __shared__ float sw[256 * 21];
    int bx = blockIdx.x, tid = threadIdx.x;
    if (bx == 0 && tid == 0) { g_cnt_xr = 0; g_cnt_bil = 0; }

    if (bx < 4096) {
        int idx = bx * 256 + tid;
        const float4* x4 = (const float4*)x;
        float4 a = x4[idx * 2];
        float4 b = x4[idx * 2 + 1];
        float v[8] = {a.x, a.y, a.z, a.w, b.x, b.y, b.z, b.w};
#pragma unroll
        for (int i = 0; i < 8; i++) {
            __half h, l;
            hsplit(v[i], &h, &l);
            g_XTh[(size_t)i * PLANE + idx] = h;
            g_XTl[(size_t)i * PLANE + idx] = l;
        }
    } else if (bx < 5120) {
        // weight: 256 (m,n) x 20 paths, coalesced read -> smem -> coalesced write
        size_t Lb = (size_t)(bx - 4096) * 256;
#pragma unroll
        for (int i = 0; i < 20; i++) {
            int li = i * 256 + tid;
            sw[(li / 20) * 21 + (li % 20)] = weight[Lb * 20 + li];
        }
        __syncthreads();
        int m = (int)((Lb + tid) >> 9), n = (int)((Lb + tid) & 511);
#pragma unroll
        for (int kb = 0; kb < 20; kb++) {
            float v = sw[tid * 21 + c_porder[kb]];
            g_WB[(size_t)c_kb_base[kb] + (size_t)m * c_kb_K[kb] + n] =
                __float2half_rn(v);
        }
    } else {
        size_t Lb = (size_t)(bx - 5120) * 256;
        int m = (int)((Lb + tid) >> 9), n = (int)((Lb + tid) & 511);
#pragma unroll
        for (int i = 0; i < 4; i++) {
            int li = i * 256 + tid;
            sw[(li >> 2) * 5 + (li & 3)] = w_right[Lb * 4 + li];
        }
        __syncthreads();
#pragma unroll
        for (int g = 0; g < 4; g++)
            g_WR[(size_t)g * WSLICE + m * 512 + n] =
                __float2half_rn(sw[tid * 5 + g]);
        __syncthreads();
#pragma unroll
        for (int i = 0; i < 4; i++) {
            int li = i * 256 + tid;
            sw[(li >> 2) * 5 + (li & 3)] = w_left[Lb * 4 + li];
        }
        __syncthreads();
#pragma unroll
        for (int g = 0; g < 4; g++)
            g_WL[(size_t)g * WSLICE + m * 512 + n] =
                __float2half_rn(sw[tid * 5 + g]);
    }
}

// pairwise qfill: thread handles 2 consecutive n; half2 loads/stores.
#define QW2(off, EXPR)                                                        \
    do {                                                                      \
        float v0, v1;                                                         \
        { const float* x_ = xa0; const float* r_ = ra0; v0 = (EXPR); }        \
        { const float* x_ = xa1; const float* r_ = ra1; v1 = (EXPR); }        \
        *(__half2*)&g_Q[(off)] = __floats2half2_rn(v0, v1);                   \
    } while (0)

__global__ void qfill_kernel(const float* __restrict__ norm_a) {
    int p = blockIdx.x * 256 + threadIdx.x;
    int base = p * 2;
    int b = base >> 9, n0 = base & 511;

    float xa0[8], xa1[8], ra0[8], ra1[8];
#pragma unroll
    for (int i = 0; i < 8; i++) {
        __half2 h = *(const __half2*)&g_XTh[(size_t)i * PLANE + base];
        __half2 l = *(const __half2*)&g_XTl[(size_t)i * PLANE + base];
        float2 hf = __half22float2(h), lf = __half22float2(l);
        xa0[i] = hf.x + lf.x;
        xa1[i] = hf.y + lf.y;
        float2 rv = *(const float2*)&g_XR[(size_t)i * PLANE + base];
        ra0[i] = rv.x;
        ra1[i] = rv.y;
    }

#pragma unroll
    for (int e = 0; e < 2; e++) {
        float* r = e ? ra1 : ra0;
        int n = n0 + e;
        float nn[4];
        nn[0] = sqrtf(r[0] * r[0]);
        nn[1] = sqrtf(r[1] * r[1] + r[2] * r[2] + r[3] * r[3]);
        nn[2] = sqrtf(r[4] * r[4] + r[5] * r[5] + r[6] * r[6]);
        nn[3] = sqrtf(r[7] * r[7]);
#pragma unroll
        for (int gg = 0; gg < 4; gg++) {
            float a = norm_a[n * 4 + gg];
            float sg = 1.0f / (1.0f + expf(-a));
            float f = sg * (nn[gg] - 1.0f) + 1.0f + 1e-6f;
            float inv = 1.0f / f;
            if (gg == 0) r[0] *= inv;
            else if (gg == 1) { r[1] *= inv; r[2] *= inv; r[3] *= inv; }
            else if (gg == 2) { r[4] *= inv; r[5] *= inv; r[6] *= inv; }
            else r[7] *= inv;
        }
    }

    {
        size_t q = QOFF0 + (size_t)b * 2048 + n0;
        QW2(q,        x_[0] * r_[0]);
        QW2(q + 512,  x_[1] * r_[1] + x_[2] * r_[2] + x_[3] * r_[3]);
        QW2(q + 1024, -(x_[4] * r_[4] + x_[5] * r_[5] + x_[6] * r_[6]));
        QW2(q + 1536, -(x_[7] * r_[7]));
    }
    {
        size_t q = QOFF1 + (size_t)(b * 3) * 3072 + n0;
        QW2(q + 0,    x_[0] * r_[1]);
        QW2(q + 512,  x_[1] * r_[0]);
        QW2(q + 1024, -x_[2] * r_[4] - x_[3] * r_[5]);
        QW2(q + 1536, x_[4] * r_[2] + x_[5] * r_[3]);
        QW2(q + 2048, -x_[6] * r_[7]);
        QW2(q + 2560, -x_[7] * r_[6]);
        QW2(q + 3072 + 0,    x_[0] * r_[2]);
        QW2(q + 3072 + 512,  x_[2] * r_[0]);
        QW2(q + 3072 + 1024, x_[1] * r_[4] - x_[3] * r_[6]);
        QW2(q + 3072 + 1536, -x_[4] * r_[1] + x_[6] * r_[3]);
        QW2(q + 3072 + 2048, x_[5] * r_[7]);
        QW2(q + 3072 + 2560, x_[7] * r_[5]);
        QW2(q + 6144 + 0,    x_[0] * r_[3]);
        QW2(q + 6144 + 512,  x_[3] * r_[0]);
        QW2(q + 6144 + 1024, x_[1] * r_[5] + x_[2] * r_[6]);
        QW2(q + 6144 + 1536, -x_[5] * r_[1] - x_[6] * r_[2]);
        QW2(q + 6144 + 2048, -x_[4] * r_[7]);
        QW2(q + 6144 + 2560, -x_[7] * r_[4]);
    }
    {
        size_t q = QOFF2 + (size_t)(b * 3) * 3072 + n0;
        QW2(q + 0,    x_[0] * r_[4]);
        QW2(q + 512,  x_[1] * r_[2] - x_[2] * r_[1]);
        QW2(q + 1024, x_[3] * r_[7]);
        QW2(q + 1536, x_[4] * r_[0]);
        QW2(q + 2048, -x_[5] * r_[6] + x_[6] * r_[5]);
        QW2(q + 2560, x_[7] * r_[3]);
        QW2(q + 3072 + 0,    x_[0] * r_[5]);
        QW2(q + 3072 + 512,  x_[1] * r_[3] - x_[3] * r_[1]);
        QW2(q + 3072 + 1024, -x_[2] * r_[7]);
        QW2(q + 3072 + 1536, x_[5] * r_[0]);
        QW2(q + 3072 + 2048, x_[4] * r_[6] - x_[6] * r_[4]);
        QW2(q + 3072 + 2560, -x_[7] * r_[2]);
        QW2(q + 6144 + 0,    x_[0] * r_[6]);
        QW2(q + 6144 + 512,  x_[2] * r_[3] - x_[3] * r_[2]);
        QW2(q + 6144 + 1024, x_[1] * r_[7]);
        QW2(q + 6144 + 1536, x_[6] * r_[0]);
        QW2(q + 6144 + 2048, -x_[4] * r_[5] + x_[5] * r_[4]);
        QW2(q + 6144 + 2560, x_[7] * r_[1]);
    }
    {
        size_t q = QOFF3 + (size_t)b * 2048 + n0;
        QW2(q,        x_[0] * r_[7]);
        QW2(q + 512,  x_[1] * r_[6] - x_[2] * r_[5] + x_[3] * r_[4]);
        QW2(q + 1024, x_[4] * r_[3] - x_[5] * r_[2] + x_[6] * r_[1]);
        QW2(q + 1536, x_[7] * r_[0]);
    }
}

__global__ void merge_out_kernel(float* __restrict__ out) {
    int idx = blockIdx.x * 256 + threadIdx.x;
    const float sc = 0.70710678118654752440f;
    float4 lo, hi;
    lo.x = g_OUT8[0 * PLANE + idx] * sc;
    lo.y = g_OUT8[1 * PLANE + idx] * sc;
    lo.z = g_OUT8[2 * PLANE + idx] * sc;
    lo.w = g_OUT8[3 * PLANE + idx] * sc;
    hi.x = g_OUT8[4 * PLANE + idx] * sc;
    hi.y = g_OUT8[5 * PLANE + idx] * sc;
    hi.z = g_OUT8[6 * PLANE + idx] * sc;
    hi.w = g_OUT8[7 * PLANE + idx] * sc;
    float4* o4 = (float4*)out;
    o4[idx * 2]     = lo;
    o4[idx * 2 + 1] = hi;
}

// ---------------------------------------------------------------------------
extern "C" void kernel_launch(void* const* d_in, const int* in_sizes, int n_in,
                              void* d_out, int out_size) {
    const float* x       = (const float*)d_in[0];
    const float* weight  = (const float*)d_in[1];
    const float* w_right = (const float*)d_in[2];
    const float* w_left  = (const float*)d_in[3];
    const float* b_left  = (const float*)d_in[4];
    const float* norm_a  = (const float*)d_in[5];
    float* out = (float*)d_out;

    int dev = 0, nsm = 148;
    cudaGetDevice(&dev);
    cudaDeviceGetAttribute(&nsm, cudaDevAttrMultiProcessorCount, dev);

    cudaFuncSetAttribute(gemm_xr,  cudaFuncAttributeMaxDynamicSharedMemorySize, XR_SMEM);
    cudaFuncSetAttribute(gemm_bil, cudaFuncAttributeMaxDynamicSharedMemorySize, BIL_SMEM);

    prep_kernel<<<6144, 256>>>(x, weight, w_right, w_left);
    gemm_xr<<<nsm, 256, XR_SMEM>>>();
    qfill_kernel<<<PLANE / 512, 256>>>(norm_a);
    gemm_bil<<<nsm, 256, BIL_SMEM>>>(b_left);
    merge_out_kernel<<<PLANE / 256, 256>>>(out);
}